// round 7
// baseline (speedup 1.0000x reference)
#include <cuda_runtime.h>
#include <cstdint>

// Problem constants
#define Bsz 32
#define Tlen 1024
#define Idim 512
#define Hdim 512

// Scratch for the input projection (device global: no allocation allowed)
__device__ float g_xproj[(size_t)Bsz * Tlen * Hdim];  // 64 MB

// ---------------------------------------------------------------------------
// packed f32x2 helpers (FFMA2 — ptxas never auto-fuses; PTX-only)
// ---------------------------------------------------------------------------
using u64 = unsigned long long;
__device__ __forceinline__ u64 pk2(float lo, float hi) {
    u64 r; asm("mov.b64 %0,{%1,%2};" : "=l"(r) : "f"(lo), "f"(hi)); return r;
}
__device__ __forceinline__ float2 upk2(u64 v) {
    float2 f; asm("mov.b64 {%0,%1},%2;" : "=f"(f.x), "=f"(f.y) : "l"(v)); return f;
}
__device__ __forceinline__ u64 fma2(u64 a, u64 b, u64 c) {
    u64 d; asm("fma.rn.f32x2 %0,%1,%2,%3;" : "=l"(d) : "l"(a), "l"(b), "l"(c)); return d;
}
__device__ __forceinline__ u64 add2(u64 a, u64 b) {
    u64 d; asm("add.rn.f32x2 %0,%1,%2;" : "=l"(d) : "l"(a), "l"(b)); return d;
}
__device__ __forceinline__ u64 mul2(u64 a, u64 b) {
    u64 d; asm("mul.rn.f32x2 %0,%1,%2;" : "=l"(d) : "l"(a), "l"(b)); return d;
}

__device__ __forceinline__ uint32_t s2u(const void* p) {
    uint32_t a;
    asm("{ .reg .u64 t; cvta.to.shared.u64 t, %1; cvt.u32.u64 %0, t; }"
        : "=r"(a) : "l"(p));
    return a;
}
__device__ __forceinline__ uint32_t mapa_rank(uint32_t laddr, uint32_t rank) {
    uint32_t r;
    asm("mapa.shared::cluster.u32 %0, %1, %2;" : "=r"(r) : "r"(laddr), "r"(rank));
    return r;
}
__device__ __forceinline__ void mbar_init(uint32_t mb, uint32_t cnt) {
    asm volatile("mbarrier.init.shared.b64 [%0], %1;" :: "r"(mb), "r"(cnt) : "memory");
}
__device__ __forceinline__ void mbar_arrive_expect_tx(uint32_t mb, uint32_t bytes) {
    asm volatile("mbarrier.arrive.expect_tx.shared.b64 _, [%0], %1;"
                 :: "r"(mb), "r"(bytes) : "memory");
}
__device__ __forceinline__ void mbar_wait_parity(uint32_t mb, uint32_t parity) {
    asm volatile(
        "{\n\t"
        ".reg .pred P;\n\t"
        "WLOOP_%=:\n\t"
        "mbarrier.try_wait.parity.acquire.cta.shared::cta.b64 P, [%0], %1, 0x989680;\n\t"
        "@P bra.uni WDONE_%=;\n\t"
        "bra.uni WLOOP_%=;\n\t"
        "WDONE_%=:\n\t"
        "}"
        :: "r"(mb), "r"(parity) : "memory");
}
__device__ __forceinline__ void bulk_dsmem(uint32_t dst, uint32_t src,
                                           uint32_t bytes, uint32_t rembar) {
    asm volatile(
        "cp.async.bulk.shared::cluster.shared::cta.mbarrier::complete_tx::bytes "
        "[%0], [%1], %2, [%3];"
        :: "r"(dst), "r"(src), "r"(bytes), "r"(rembar) : "memory");
}
__device__ __forceinline__ void fence_proxy_async_cta() {
    asm volatile("fence.proxy.async.shared::cta;" ::: "memory");
}
__device__ __forceinline__ void cluster_sync_asm() {
    asm volatile("barrier.cluster.arrive.aligned;" ::: "memory");
    asm volatile("barrier.cluster.wait.aligned;" ::: "memory");
}
__device__ __forceinline__ u64 shflx2(u64 v, int m) {
    float2 f = upk2(v);
    f.x = __shfl_xor_sync(0xFFFFFFFFu, f.x, m);
    f.y = __shfl_xor_sync(0xFFFFFFFFu, f.y, m);
    return pk2(f.x, f.y);
}
// Fast branch-free tanh (rel err ~1e-6, fine vs 1e-3 tolerance)
__device__ __forceinline__ float ftanh(float x) {
    float ax = fabsf(x);
    float e = __expf(-2.0f * ax);
    float r = __fdividef(1.0f - e, 1.0f + e);
    return copysignf(r, x);
}

// ---------------------------------------------------------------------------
// Kernel 1: xproj[m, h] = sum_i X[m, i] * Wih[h, i] + bih[h] + bhh[h]
//   fp32 SGEMM 128x128x16, 8x8 micro-tile, inner loop in fma.rn.f32x2
// ---------------------------------------------------------------------------
__global__ void __launch_bounds__(256) xproj_kernel(
    const float* __restrict__ X,     // [32768, 512]
    const float* __restrict__ Wih,   // [512, 512]
    const float* __restrict__ bih,
    const float* __restrict__ bhh)
{
    const int BM = 128, BN = 128, BK = 16;
    __shared__ __align__(16) float As[BK][BM + 4];
    __shared__ __align__(16) float Bs[BK][BN + 4];

    const int tid = threadIdx.x;
    const int m0 = blockIdx.y * BM;
    const int n0 = blockIdx.x * BN;
    const int tx = tid & 15;
    const int ty = tid >> 4;

    u64 acc2[8][4];
#pragma unroll
    for (int i = 0; i < 8; ++i)
#pragma unroll
        for (int j = 0; j < 4; ++j) acc2[i][j] = 0ull;

    for (int k0 = 0; k0 < Idim; k0 += BK) {
#pragma unroll
        for (int q = 0; q < 2; ++q) {
            int lin = tid + 256 * q;
            int m = lin >> 2;
            int kv = (lin & 3) << 2;
            float4 va = *(const float4*)(X + (size_t)(m0 + m) * Idim + k0 + kv);
            As[kv + 0][m] = va.x; As[kv + 1][m] = va.y;
            As[kv + 2][m] = va.z; As[kv + 3][m] = va.w;
            float4 vb = *(const float4*)(Wih + (size_t)(n0 + m) * Idim + k0 + kv);
            Bs[kv + 0][m] = vb.x; Bs[kv + 1][m] = vb.y;
            Bs[kv + 2][m] = vb.z; Bs[kv + 3][m] = vb.w;
        }
        __syncthreads();

#pragma unroll
        for (int kk = 0; kk < BK; ++kk) {
            float ra[8];
            *(float4*)&ra[0] = *(const float4*)&As[kk][ty * 8];
            *(float4*)&ra[4] = *(const float4*)&As[kk][ty * 8 + 4];
            ulonglong2 rbA = *(const ulonglong2*)&Bs[kk][tx * 8];
            ulonglong2 rbB = *(const ulonglong2*)&Bs[kk][tx * 8 + 4];
            u64 rb2[4] = { rbA.x, rbA.y, rbB.x, rbB.y };
#pragma unroll
            for (int i = 0; i < 8; ++i) {
                u64 rap = pk2(ra[i], ra[i]);
#pragma unroll
                for (int j = 0; j < 4; ++j)
                    acc2[i][j] = fma2(rap, rb2[j], acc2[i][j]);
            }
        }
        __syncthreads();
    }

    u64 bs2[4];
#pragma unroll
    for (int j = 0; j < 4; ++j) {
        float blo = bih[n0 + tx * 8 + 2 * j] + bhh[n0 + tx * 8 + 2 * j];
        float bhi = bih[n0 + tx * 8 + 2 * j + 1] + bhh[n0 + tx * 8 + 2 * j + 1];
        bs2[j] = pk2(blo, bhi);
    }

#pragma unroll
    for (int i = 0; i < 8; ++i) {
        float2 p0 = upk2(add2(acc2[i][0], bs2[0]));
        float2 p1 = upk2(add2(acc2[i][1], bs2[1]));
        float2 p2 = upk2(add2(acc2[i][2], bs2[2]));
        float2 p3 = upk2(add2(acc2[i][3], bs2[3]));
        float* crow = g_xproj + (size_t)(m0 + ty * 8 + i) * Hdim + n0 + tx * 8;
        *(float4*)(crow)     = make_float4(p0.x, p0.y, p1.x, p1.y);
        *(float4*)(crow + 4) = make_float4(p2.x, p2.y, p3.x, p3.y);
    }
}

// ---------------------------------------------------------------------------
// Kernel 2: the recurrence — all-to-all of M-partials, TWO PIPELINED STREAMS.
//   The two batches run as independent streams offset by half a step:
//   [wait0 A0 sync B0+send0][wait1 A1 sync B1+send1]. While stream 0's
//   partials cross the DSMEM fabric, the SM computes stream 1 (and vice
//   versa) — fabric latency is hidden behind the other stream's compute.
//   Everything per-step is duplicated per stream: arr/stg buffers, barriers,
//   hloc, register M-rings. Weights (Whh columns) shared in registers.
// ---------------------------------------------------------------------------
__global__ void __launch_bounds__(256, 1) __cluster_dims__(8, 1, 1)
rnn_kernel(const float* __restrict__ Whh,   // [512, 512]
           const float* __restrict__ kern,  // [4]
           float* __restrict__ out_states,  // [B, T, H]
           float* __restrict__ out_last)    // [B, H]
{
    __shared__ __align__(16) float arr[2][2][8][64];  // 8KB [s][slot][src][64]
    __shared__ __align__(16) float stg[2][2][8][64];  // 8KB [s][slot][dst][64]
    __shared__ __align__(16) float hloc[2][64];       // h_t[own rows] per stream
    __shared__ __align__(16) float xs[2][2][8][64];   // 8KB [buf][b][t&7][64]
    __shared__ __align__(16) float xout[2][2][8][64]; // 8KB [buf][b][t&7][64]
    __shared__ __align__(8)  u64 mbars[4];            // [s*2 + slot]

    const int tid   = threadIdx.x;
    const int lane  = tid & 31;
    const int w     = tid >> 5;            // warp id == destination peer
    const int slice = blockIdx.x;          // cluster rank 0..7
    const int grp   = blockIdx.y;          // 0..15
    const int b0    = grp * 2;

    // Register weights: rows 64w+2*lane, +1 of Whh, columns [64*slice, +64),
    // packed along K (pairs of adjacent columns).
    u64 wR0[32], wR1[32];
    {
        const float* r0p = Whh + (size_t)(64 * w + 2 * lane) * Hdim + 64 * slice;
        const float* r1p = r0p + Hdim;
#pragma unroll
        for (int m = 0; m < 16; ++m) {
            ulonglong2 u0 = *(const ulonglong2*)(r0p + 4 * m);
            ulonglong2 u1 = *(const ulonglong2*)(r1p + 4 * m);
            wR0[2 * m] = u0.x; wR0[2 * m + 1] = u0.y;
            wR1[2 * m] = u1.x; wR1[2 * m + 1] = u1.y;
        }
    }
    const u64 kk0 = pk2(kern[0], kern[0]), kk1 = pk2(kern[1], kern[1]);
    const u64 kk2 = pk2(kern[2], kern[2]), kk3 = pk2(kern[3], kern[3]);

    // Init + arm tx-barriers (count 1, expect 7*256 B per stream-slot)
    const uint32_t mb0 = s2u(&mbars[0]);
    if (tid == 0) {
#pragma unroll
        for (int q = 0; q < 4; ++q) {
            mbar_init(mb0 + q * 8, 1);
            mbar_arrive_expect_tx(mb0 + q * 8, 7 * 256);
        }
    }

    // Per-warp remote targets (peer w): arr base + barrier base on rank w
    const uint32_t arr_rb = mapa_rank(s2u(arr), w);   // peer w's arr base
    const uint32_t bar_rb = mapa_rank(mb0, w);        // peer w's barrier base

    cluster_sync_asm();   // barrier init visible cluster-wide

    // xproj staging: one float4 per thread per 8-step group
    const int pb  = tid >> 7;
    const int pt  = (tid >> 4) & 7;
    const int pu  = tid & 15;
    const float* xsrc = g_xproj + (size_t)(b0 + pb) * Tlen * Hdim
                        + (size_t)pt * Hdim + slice * 64 + pu * 4;
    *(float4*)&xs[0][pb][pt][pu * 4] = *(const float4*)(xsrc);        // group 0
    float4 xpre = *(const float4*)(xsrc + 8 * Hdim);                  // group 1
    __syncthreads();

    // Phase-A roles: pair group + source lane
    const int pairg = tid >> 3;    // 0..31 : row pair (rows 2p, 2p+1)
    const int lsrc  = tid & 7;     // source rank this lane gathers

    // Register M-rings per stream: M_{t-2}, M_{t-3}, M_{t-4}, packed (row2p,row2p+1)
    u64 rg0[2] = {0ull, 0ull}, rg1[2] = {0ull, 0ull}, rg2[2] = {0ull, 0ull};

    for (int t = 0; t < Tlen; ++t) {
#pragma unroll
        for (int s = 0; s < 2; ++s) {
            // ---- Phase A(s): wait, gather M_{t-1}, taps, tanh -> hloc[s] ----
            u64 Mt1 = 0ull;
            if (t > 0) {
                const uint32_t bar = mb0 + (s * 2 + ((t - 1) & 1)) * 8;
                mbar_wait_parity(bar, ((t - 1) >> 1) & 1);
                if (tid == 0)
                    mbar_arrive_expect_tx(bar, 7 * 256);   // re-arm

                // Gather: lane lsrc reads its source's u64 (rows 2p,2p+1)
                u64 v = *(const u64*)&arr[s][(t - 1) & 1][lsrc]
                                        [((pairg + 2 * lsrc) & 31) * 2];
                v = add2(v, shflx2(v, 1));
                v = add2(v, shflx2(v, 2));
                v = add2(v, shflx2(v, 4));
                Mt1 = v;                    // all 8 lanes hold full M pair
            }

            // Stage next xproj group; flush previous output group (s==0 only)
            if (s == 0 && (t & 7) == 0) {
                int g = t >> 3;
                *(float4*)&xs[(g + 1) & 1][pb][pt][pu * 4] = xpre;
                if (t + 16 < Tlen)
                    xpre = *(const float4*)(xsrc + (size_t)(t + 16) * Hdim);
                if (t > 0) {
                    // flush group g-1 (writes ordered by last step's syncs)
                    *(float4*)(out_states + (size_t)(b0 + pb) * Tlen * Hdim
                               + (size_t)(t - 8 + pt) * Hdim + slice * 64 + pu * 4)
                        = *(const float4*)&xout[(g - 1) & 1][pb][pt][pu * 4];
                }
            }

            // 4-tap Lagrange on the register M-ring
            u64 rr = fma2(kk0, Mt1,
                     fma2(kk1, rg0[s], fma2(kk2, rg1[s], mul2(kk3, rg2[s]))));
            rg2[s] = rg1[s]; rg1[s] = rg0[s]; rg0[s] = Mt1;

            if (lsrc < 2) {                 // lanes 0,1: rows 2p, 2p+1
                float2 rf = upk2(rr);
                float pre = (lsrc == 0) ? rf.x : rf.y;
                int row = 2 * pairg + lsrc;
                float val = ftanh(pre + xs[(t >> 3) & 1][s][t & 7][row]);
                hloc[s][row] = val;
                xout[(t >> 3) & 1][s][t & 7][row] = val;
                if (t == Tlen - 1)
                    out_last[(size_t)(b0 + s) * Hdim + slice * 64 + row] = val;
            }

            __syncthreads();   // hloc[s] ready; orders own-arr/stg reuse

            // ---- Phase B(s): per-warp partial chunk GEMV + immediate send ----
            if (t < Tlen - 1) {
                u64 aA = 0ull, cA = 0ull, aB = 0ull, cB = 0ull;
#pragma unroll
                for (int m = 0; m < 16; ++m) {
                    ulonglong2 h = *(const ulonglong2*)&hloc[s][4 * m];
                    aA = fma2(wR0[2 * m],     h.x, aA);
                    cA = fma2(wR0[2 * m + 1], h.y, cA);
                    aB = fma2(wR1[2 * m],     h.x, aB);
                    cB = fma2(wR1[2 * m + 1], h.y, cB);
                }
                float2 fA = upk2(add2(aA, cA));
                float2 fB = upk2(add2(aB, cB));
                u64 o = pk2(fA.x + fA.y, fB.x + fB.y);   // rows 2lane, 2lane+1

                float* dstp = (w == slice) ? &arr[s][t & 1][slice][0]
                                           : &stg[s][t & 1][w][0];
                *(u64*)(dstp + ((lane + 2 * slice) & 31) * 2) = o;
                __syncwarp();
                if (w != slice && lane == 0) {
                    fence_proxy_async_cta();
                    const uint32_t off =
                        (uint32_t)(((s * 2 + (t & 1)) * 8 + slice) * 256);
                    bulk_dsmem(arr_rb + off,
                               s2u(&stg[s][t & 1][w][0]), 256,
                               bar_rb + (uint32_t)((s * 2 + (t & 1)) * 8));
                }
            }
        }
    }

    // Final output group (t = 1016..1023, buf 1)
    __syncthreads();
    *(float4*)(out_states + (size_t)(b0 + pb) * Tlen * Hdim
               + (size_t)(Tlen - 8 + pt) * Hdim + slice * 64 + pu * 4)
        = *(const float4*)&xout[1][pb][pt][pu * 4];

    // No CTA may exit while peers' bulk copies could still target it
    cluster_sync_asm();
}

// ---------------------------------------------------------------------------
extern "C" void kernel_launch(void* const* d_in, const int* in_sizes, int n_in,
                              void* d_out, int out_size)
{
    (void)in_sizes; (void)n_in; (void)out_size;
    const float* x    = (const float*)d_in[0];   // [32, 1024, 512]
    const float* Wih  = (const float*)d_in[1];   // [512, 512]
    const float* Whh  = (const float*)d_in[2];   // [512, 512]
    const float* bih  = (const float*)d_in[3];   // [512]
    const float* bhh  = (const float*)d_in[4];   // [512]
    const float* kern = (const float*)d_in[5];   // [4]

    float* out        = (float*)d_out;
    float* out_states = out;                                   // [32,1024,512]
    float* out_last   = out + (size_t)Bsz * Tlen * Hdim;       // [32,512]

    dim3 gg(Hdim / 128, (Bsz * Tlen) / 128);   // (4, 256)
    xproj_kernel<<<gg, 256>>>(x, Wih, bih, bhh);

    dim3 gr(8, 16);
    rnn_kernel<<<gr, 256>>>(Whh, kern, out_states, out_last);
}